// round 1
// baseline (speedup 1.0000x reference)
#include <cuda_runtime.h>
#include <math.h>

#define NPRI  10647
#define BB    16
#define LL    50
#define NCLS  80

// prior layout: level0 [0,507), level1 [507,2535), level2 [2535,10647)
// within level: n_loc = (i*S + j)*3 + a

__device__ float4        g_prior_box[NPRI];          // px, py, pw, ph  (normalized)
__device__ float4        g_prior_aux[NPRI];          // col(j), row(i), aw_pix, ah_pix
__device__ float         g_tall[BB * LL * 4];        // target coords per (b,label)
__device__ int           g_winner[BB * NPRI];        // segment max of g = b*50+l, init -1
__device__ unsigned char g_supp[BB * NPRI];          // suppressed flag
__device__ unsigned int  g_clsmask[BB * NPRI * 3];   // 80-bit class target bitmask
__device__ float         g_acc[9];                   // [lvl*3 + {obj,coord,cls}] sums

// ---------------------------------------------------------------- init
__global__ void k_init() {
    int i = blockIdx.x * blockDim.x + threadIdx.x;
    if (i < BB * NPRI) {
        g_winner[i] = -1;
        g_supp[i] = 0;
        g_clsmask[3 * i + 0] = 0u;
        g_clsmask[3 * i + 1] = 0u;
        g_clsmask[3 * i + 2] = 0u;
    }
    if (i < 9) g_acc[i] = 0.f;
}

// ---------------------------------------------------------------- priors
__global__ void k_priors() {
    int n = blockIdx.x * blockDim.x + threadIdx.x;
    if (n >= NPRI) return;
    const int AW[3][3] = {{116, 156, 373}, {30, 62, 59}, {10, 16, 33}};
    const int AH[3][3] = {{90, 198, 326}, {61, 45, 119}, {13, 30, 23}};
    int l, S, off;
    if (n < 507)       { l = 0; S = 13; off = 0; }
    else if (n < 2535) { l = 1; S = 26; off = 507; }
    else               { l = 2; S = 52; off = 2535; }
    int nl = n - off;
    int a = nl % 3;
    int cell = nl / 3;
    int i = cell / S, j = cell % S;
    // match numpy: computed in python double, rounded to f32
    double w = AW[l][a] / 416.0;
    double h = AH[l][a] / 416.0;
    double cx = (j + 0.5) / (double)S;
    double cy = (i + 0.5) / (double)S;
    g_prior_box[n] = make_float4((float)(cx - 0.5 * w), (float)(cy - 0.5 * h),
                                 (float)w, (float)h);
    g_prior_aux[n] = make_float4((float)j, (float)i, (float)AW[l][a], (float)AH[l][a]);
}

// ---------------------------------------------------------------- targets
// one block per (b, label); 256 threads
__global__ void __launch_bounds__(256) k_targets(const float* __restrict__ labels) {
    __shared__ float sious[NPRI];
    __shared__ float sred[256];
    __shared__ int   scnt[257];

    int b  = blockIdx.x / LL;
    int lb = blockIdx.x % LL;
    int tid = threadIdx.x;

    const float* lab = labels + (size_t)(b * LL + lb) * 5;
    float cls = lab[0];
    if (cls < 0.0f) return;   // invalid label: contributes nothing
    float bx = lab[1], by = lab[2], bw = lab[3], bh = lab[4];
    float barea = __fmul_rn(bw, bh);
    float bxe = __fadd_rn(bx, bw);
    float bye = __fadd_rn(by, bh);

    // pass 1: strided iou compute into smem (coalesced prior loads)
    float lmax = -1e30f;
    for (int n = tid; n < NPRI; n += 256) {
        float4 p = g_prior_box[n];
        float ix = fmaxf(p.x, bx);
        float iy = fmaxf(p.y, by);
        float ax = fminf(__fadd_rn(p.x, p.z), bxe);
        float ay = fminf(__fadd_rn(p.y, p.w), bye);
        float inter = __fmul_rn(fmaxf(__fsub_rn(ax, ix), 0.0f),
                                fmaxf(__fsub_rn(ay, iy), 0.0f));
        float denom = __fsub_rn(__fadd_rn(__fmul_rn(p.z, p.w), barea), inter);
        float iou = __fdiv_rn(inter, denom);
        sious[n] = iou;
        lmax = fmaxf(lmax, iou);
        if (iou >= 0.5f) g_supp[b * NPRI + n] = 1;
    }
    sred[tid] = lmax;
    __syncthreads();
    for (int s = 128; s > 0; s >>= 1) {
        if (tid < s) sred[tid] = fmaxf(sred[tid], sred[tid + s]);
        __syncthreads();
    }
    float m = sred[0];

    // pass 2: tie counting in contiguous chunks (ordered)
    const int CH = 42;                     // ceil(10647/256)
    int start = tid * CH;
    int end = min(start + CH, NPRI);
    int cnt = 0;
    for (int n = start; n < end; n++)
        if (sious[n] == m) cnt++;
    scnt[tid] = cnt;
    __syncthreads();
    if (tid == 0) {
        int run = 0;
        for (int t = 0; t < 256; t++) { int c = scnt[t]; scnt[t] = run; run += c; }
        scnt[256] = run;
    }
    __syncthreads();
    int k = scnt[256];
    int rank = (k - 1) / 2 + 1;
    int excl = scnt[tid];

    if (excl < rank && rank <= excl + cnt) {
        int need = rank - excl;
        int idx = -1;
        for (int n = start; n < end; n++) {
            if (sious[n] == m && --need == 0) { idx = n; break; }
        }
        float4 aux = g_prior_aux[idx];
        float Sf = (idx < 507) ? 13.f : (idx < 2535) ? 26.f : 52.f;
        float dx = fminf(fmaxf((bx + 0.5f * bw) * Sf - aux.x, 1e-6f), 0.999999f);
        float dy = fminf(fmaxf((by + 0.5f * bh) * Sf - aux.y, 1e-6f), 0.999999f);
        int gl = b * LL + lb;
        g_tall[gl * 4 + 0] = logf(dx / (1.0f - dx));
        g_tall[gl * 4 + 1] = logf(dy / (1.0f - dy));
        g_tall[gl * 4 + 2] = logf(bw * 416.0f / aux.z);
        g_tall[gl * 4 + 3] = logf(bh * 416.0f / aux.w);
        atomicMax(&g_winner[b * NPRI + idx], gl);
        int ci = (int)cls;
        atomicOr(&g_clsmask[(size_t)(b * NPRI + idx) * 3 + (ci >> 5)], 1u << (ci & 31));
    }
}

// ---------------------------------------------------------------- loss
__global__ void __launch_bounds__(256) k_loss(const float* __restrict__ o0,
                                              const float* __restrict__ o1,
                                              const float* __restrict__ o2) {
    __shared__ float sacc[9];
    if (threadIdx.x < 9) sacc[threadIdx.x] = 0.f;
    __syncthreads();

    int t = blockIdx.x * 256 + threadIdx.x;
    if (t < BB * NPRI) {
        int b = t / NPRI;
        int r = t % NPRI;
        int lvl, SS_, off;
        const float* out;
        if (r < 507)       { lvl = 0; SS_ = 169;  off = 0;    out = o0; }
        else if (r < 2535) { lvl = 1; SS_ = 676;  off = 507;  out = o1; }
        else               { lvl = 2; SS_ = 2704; off = 2535; out = o2; }
        int rl = r - off;
        int a = rl / SS_;
        int cell = rl % SS_;
        int n = off + cell * 3 + a;
        int gn = b * NPRI + n;
        const float* base = out + (size_t)b * 255 * SS_ + (size_t)a * 85 * SS_ + cell;

        int w = g_winner[gn];
        bool chosen = (w >= 0);
        bool om = chosen || !g_supp[gn];

        if (om) {
            float x = base[4 * SS_];
            float s = 1.f / (1.f + expf(-x));
            float lg = chosen ? fmaxf(logf(s), -100.f) : fmaxf(logf(1.f - s), -100.f);
            atomicAdd(&sacc[lvl * 3 + 0], -lg);
        }
        if (chosen) {
            int gl4 = w * 4;
            float csum = 0.f;
            #pragma unroll
            for (int k = 0; k < 4; k++) {
                float d = base[k * SS_] - g_tall[gl4 + k];
                csum += d * d;
            }
            unsigned int m0 = g_clsmask[(size_t)gn * 3 + 0];
            unsigned int m1 = g_clsmask[(size_t)gn * 3 + 1];
            unsigned int m2 = g_clsmask[(size_t)gn * 3 + 2];
            float ksum = 0.f;
            for (int k = 0; k < NCLS; k++) {
                float x = base[(5 + k) * SS_];
                float s = 1.f / (1.f + expf(-x));
                unsigned int bit =
                    ((k < 32 ? (m0 >> k) : k < 64 ? (m1 >> (k - 32)) : (m2 >> (k - 64))) & 1u);
                float lg = bit ? fmaxf(logf(s), -100.f) : fmaxf(logf(1.f - s), -100.f);
                ksum -= lg;
            }
            atomicAdd(&sacc[lvl * 3 + 1], csum);
            atomicAdd(&sacc[lvl * 3 + 2], ksum);
        }
    }
    __syncthreads();
    if (threadIdx.x < 9 && sacc[threadIdx.x] != 0.f)
        atomicAdd(&g_acc[threadIdx.x], sacc[threadIdx.x]);
}

// ---------------------------------------------------------------- final
__global__ void k_final(float* __restrict__ outp) {
    float obj = 0.f, crd = 0.f, cl = 0.f;
    const float ss[3] = {169.f, 676.f, 2704.f};
    for (int l = 0; l < 3; l++) {
        obj += g_acc[l * 3 + 0] / (48.f * ss[l]);     // B*A       = 48
        crd += g_acc[l * 3 + 1] / (192.f * ss[l]);    // B*A*4     = 192
        cl  += g_acc[l * 3 + 2] / (3840.f * ss[l]);   // B*A*80    = 3840
    }
    outp[0] = obj;
    outp[1] = crd;
    outp[2] = cl;
}

// ---------------------------------------------------------------- launch
extern "C" void kernel_launch(void* const* d_in, const int* in_sizes, int n_in,
                              void* d_out, int out_size) {
    const float *o0 = nullptr, *o1 = nullptr, *o2 = nullptr, *lab = nullptr;
    for (int i = 0; i < n_in; i++) {
        switch (in_sizes[i]) {
            case 16 * 255 * 13 * 13: o0 = (const float*)d_in[i]; break;
            case 16 * 255 * 26 * 26: o1 = (const float*)d_in[i]; break;
            case 16 * 255 * 52 * 52: o2 = (const float*)d_in[i]; break;
            case 16 * 1 * 50 * 5:    lab = (const float*)d_in[i]; break;
            default: break;
        }
    }
    // fallback to positional order if size matching failed
    if (!o0 || !o1 || !o2 || !lab) {
        o0 = (const float*)d_in[0];
        o1 = (const float*)d_in[1];
        o2 = (const float*)d_in[2];
        lab = (const float*)d_in[3];
    }

    int totBN = BB * NPRI;
    k_init<<<(totBN + 255) / 256, 256>>>();
    k_priors<<<(NPRI + 255) / 256, 256>>>();
    k_targets<<<BB * LL, 256>>>(lab);
    k_loss<<<(totBN + 255) / 256, 256>>>(o0, o1, o2);
    k_final<<<1, 1>>>((float*)d_out);
}

// round 2
// speedup vs baseline: 1.4126x; 1.4126x over previous
#include <cuda_runtime.h>
#include <math.h>

#define NPRI  10647
#define BB    16
#define LL    50
#define NCLS  80

// prior layout: level0 [0,507), level1 [507,2535), level2 [2535,10647)
// within level: n_loc = (i*S + j)*3 + a

__device__ float4        g_prior_box[NPRI];          // px, py, pw, ph  (normalized)
__device__ float4        g_prior_aux[NPRI];          // col(j), row(i), aw_pix, ah_pix
__device__ float         g_tall[BB * LL * 4];        // target coords per (b,label)
__device__ int           g_winner[BB * NPRI];        // segment max of g = b*50+l, init -1
__device__ unsigned char g_supp[BB * NPRI];          // suppressed flag
__device__ unsigned int  g_clsmask[BB * NPRI * 3];   // 80-bit class target bitmask
__device__ float         g_acc[9];                   // [lvl*3 + {obj,coord,cls}] sums

// min(softplus(y), 100) == min(-log(sigmoid(-y)), 100): the clamped BCE term
__device__ __forceinline__ float bce_term(float y) {
    float sp = fmaxf(y, 0.0f) + __logf(1.0f + __expf(-fabsf(y)));
    return fminf(sp, 100.0f);
}

// ---------------------------------------------------------------- setup (init + priors fused)
__global__ void k_setup() {
    int i = blockIdx.x * blockDim.x + threadIdx.x;
    if (i < BB * NPRI) {
        g_winner[i] = -1;
        g_supp[i] = 0;
        g_clsmask[3 * i + 0] = 0u;
        g_clsmask[3 * i + 1] = 0u;
        g_clsmask[3 * i + 2] = 0u;
    }
    if (i < 9) g_acc[i] = 0.f;

    if (i < NPRI) {
        const int AW[3][3] = {{116, 156, 373}, {30, 62, 59}, {10, 16, 33}};
        const int AH[3][3] = {{90, 198, 326}, {61, 45, 119}, {13, 30, 23}};
        int l, S, off;
        if (i < 507)       { l = 0; S = 13; off = 0; }
        else if (i < 2535) { l = 1; S = 26; off = 507; }
        else               { l = 2; S = 52; off = 2535; }
        int nl = i - off;
        int a = nl % 3;
        int cell = nl / 3;
        int ri = cell / S, cj = cell % S;
        // match numpy: computed in python double, rounded to f32
        double w = AW[l][a] / 416.0;
        double h = AH[l][a] / 416.0;
        double cx = (cj + 0.5) / (double)S;
        double cy = (ri + 0.5) / (double)S;
        g_prior_box[i] = make_float4((float)(cx - 0.5 * w), (float)(cy - 0.5 * h),
                                     (float)w, (float)h);
        g_prior_aux[i] = make_float4((float)cj, (float)ri, (float)AW[l][a], (float)AH[l][a]);
    }
}

// ---------------------------------------------------------------- targets
// one block per (b, label); 256 threads
__global__ void __launch_bounds__(256) k_targets(const float* __restrict__ labels) {
    __shared__ float sious[NPRI];
    __shared__ float sred[256];
    __shared__ int   scnt[257];

    int b  = blockIdx.x / LL;
    int lb = blockIdx.x % LL;
    int tid = threadIdx.x;

    const float* lab = labels + (size_t)(b * LL + lb) * 5;
    float cls = lab[0];
    if (cls < 0.0f) return;   // invalid label: contributes nothing
    float bx = lab[1], by = lab[2], bw = lab[3], bh = lab[4];
    float barea = __fmul_rn(bw, bh);
    float bxe = __fadd_rn(bx, bw);
    float bye = __fadd_rn(by, bh);

    // pass 1: strided iou compute into smem (coalesced prior loads)
    float lmax = -1e30f;
    for (int n = tid; n < NPRI; n += 256) {
        float4 p = g_prior_box[n];
        float ix = fmaxf(p.x, bx);
        float iy = fmaxf(p.y, by);
        float ax = fminf(__fadd_rn(p.x, p.z), bxe);
        float ay = fminf(__fadd_rn(p.y, p.w), bye);
        float inter = __fmul_rn(fmaxf(__fsub_rn(ax, ix), 0.0f),
                                fmaxf(__fsub_rn(ay, iy), 0.0f));
        float denom = __fsub_rn(__fadd_rn(__fmul_rn(p.z, p.w), barea), inter);
        float iou = __fdiv_rn(inter, denom);
        sious[n] = iou;
        lmax = fmaxf(lmax, iou);
        if (iou >= 0.5f) g_supp[b * NPRI + n] = 1;
    }
    sred[tid] = lmax;
    __syncthreads();
    for (int s = 128; s > 0; s >>= 1) {
        if (tid < s) sred[tid] = fmaxf(sred[tid], sred[tid + s]);
        __syncthreads();
    }
    float m = sred[0];

    // pass 2: tie counting in contiguous chunks (ordered)
    const int CH = 42;                     // ceil(10647/256)
    int start = tid * CH;
    int end = min(start + CH, NPRI);
    int cnt = 0;
    for (int n = start; n < end; n++)
        if (sious[n] == m) cnt++;
    scnt[tid] = cnt;
    __syncthreads();
    if (tid == 0) {
        int run = 0;
        for (int t = 0; t < 256; t++) { int c = scnt[t]; scnt[t] = run; run += c; }
        scnt[256] = run;
    }
    __syncthreads();
    int k = scnt[256];
    int rank = (k - 1) / 2 + 1;
    int excl = scnt[tid];

    if (excl < rank && rank <= excl + cnt) {
        int need = rank - excl;
        int idx = -1;
        for (int n = start; n < end; n++) {
            if (sious[n] == m && --need == 0) { idx = n; break; }
        }
        float4 aux = g_prior_aux[idx];
        float Sf = (idx < 507) ? 13.f : (idx < 2535) ? 26.f : 52.f;
        float dx = fminf(fmaxf((bx + 0.5f * bw) * Sf - aux.x, 1e-6f), 0.999999f);
        float dy = fminf(fmaxf((by + 0.5f * bh) * Sf - aux.y, 1e-6f), 0.999999f);
        int gl = b * LL + lb;
        g_tall[gl * 4 + 0] = logf(dx / (1.0f - dx));
        g_tall[gl * 4 + 1] = logf(dy / (1.0f - dy));
        g_tall[gl * 4 + 2] = logf(bw * 416.0f / aux.z);
        g_tall[gl * 4 + 3] = logf(bh * 416.0f / aux.w);
        atomicMax(&g_winner[b * NPRI + idx], gl);
        int ci = (int)cls;
        atomicOr(&g_clsmask[(size_t)(b * NPRI + idx) * 3 + (ci >> 5)], 1u << (ci & 31));
    }
}

// ---------------------------------------------------------------- loss
// warp-cooperative: chosen priors (~320 total) are processed by the whole warp
__global__ void __launch_bounds__(256) k_loss(const float* __restrict__ o0,
                                              const float* __restrict__ o1,
                                              const float* __restrict__ o2) {
    __shared__ float sacc[9];
    if (threadIdx.x < 9) sacc[threadIdx.x] = 0.f;
    __syncthreads();

    int t = blockIdx.x * 256 + threadIdx.x;
    bool active = t < BB * NPRI;

    int lvl = 0, SS_ = 1, gn = 0, w = -1;
    const float* base = nullptr;
    bool chosen = false;
    float objc = 0.f;

    if (active) {
        int b = t / NPRI;
        int r = t % NPRI;
        int off;
        const float* out;
        if (r < 507)       { lvl = 0; SS_ = 169;  off = 0;    out = o0; }
        else if (r < 2535) { lvl = 1; SS_ = 676;  off = 507;  out = o1; }
        else               { lvl = 2; SS_ = 2704; off = 2535; out = o2; }
        int rl = r - off;
        int a = rl / SS_;
        int cell = rl % SS_;
        int n = off + cell * 3 + a;
        gn = b * NPRI + n;
        base = out + (size_t)b * 255 * SS_ + (size_t)a * 85 * SS_ + cell;

        w = g_winner[gn];
        chosen = (w >= 0);
        bool om = chosen || !g_supp[gn];

        if (om) {
            float x = base[4 * SS_];
            objc = bce_term(chosen ? -x : x);
        }
    }
    if (objc != 0.f) atomicAdd(&sacc[lvl * 3 + 0], objc);

    // cooperative chosen handling: whole warp processes each chosen lane's prior
    unsigned cmask = __ballot_sync(0xffffffffu, chosen);
    int myl = threadIdx.x & 31;
    while (cmask) {
        int src = __ffs(cmask) - 1;
        cmask &= cmask - 1;
        unsigned long long bp = __shfl_sync(0xffffffffu, (unsigned long long)base, src);
        const float* cb = (const float*)bp;
        int cw  = __shfl_sync(0xffffffffu, w, src);
        int cgn = __shfl_sync(0xffffffffu, gn, src);
        int cS  = __shfl_sync(0xffffffffu, SS_, src);
        int cl  = __shfl_sync(0xffffffffu, lvl, src);

        float csum = 0.f;
        if (myl < 4) {
            float d = cb[myl * cS] - g_tall[cw * 4 + myl];
            csum = d * d;
        }
        float ksum = 0.f;
        #pragma unroll
        for (int kb = 0; kb < 3; kb++) {
            int k = myl + kb * 32;
            if (k < NCLS) {
                float x = cb[(5 + k) * cS];
                unsigned mw = g_clsmask[(size_t)cgn * 3 + (k >> 5)];
                bool bit = (mw >> (k & 31)) & 1u;
                ksum += bce_term(bit ? -x : x);
            }
        }
        #pragma unroll
        for (int o = 16; o > 0; o >>= 1) {
            csum += __shfl_xor_sync(0xffffffffu, csum, o);
            ksum += __shfl_xor_sync(0xffffffffu, ksum, o);
        }
        if (myl == 0) {
            atomicAdd(&sacc[cl * 3 + 1], csum);
            atomicAdd(&sacc[cl * 3 + 2], ksum);
        }
    }

    __syncthreads();
    if (threadIdx.x < 9 && sacc[threadIdx.x] != 0.f)
        atomicAdd(&g_acc[threadIdx.x], sacc[threadIdx.x]);
}

// ---------------------------------------------------------------- final
__global__ void k_final(float* __restrict__ outp) {
    float obj = 0.f, crd = 0.f, cl = 0.f;
    const float ss[3] = {169.f, 676.f, 2704.f};
    for (int l = 0; l < 3; l++) {
        obj += g_acc[l * 3 + 0] / (48.f * ss[l]);     // B*A       = 48
        crd += g_acc[l * 3 + 1] / (192.f * ss[l]);    // B*A*4     = 192
        cl  += g_acc[l * 3 + 2] / (3840.f * ss[l]);   // B*A*80    = 3840
    }
    outp[0] = obj;
    outp[1] = crd;
    outp[2] = cl;
}

// ---------------------------------------------------------------- launch
extern "C" void kernel_launch(void* const* d_in, const int* in_sizes, int n_in,
                              void* d_out, int out_size) {
    const float *o0 = nullptr, *o1 = nullptr, *o2 = nullptr, *lab = nullptr;
    for (int i = 0; i < n_in; i++) {
        switch (in_sizes[i]) {
            case 16 * 255 * 13 * 13: o0 = (const float*)d_in[i]; break;
            case 16 * 255 * 26 * 26: o1 = (const float*)d_in[i]; break;
            case 16 * 255 * 52 * 52: o2 = (const float*)d_in[i]; break;
            case 16 * 1 * 50 * 5:    lab = (const float*)d_in[i]; break;
            default: break;
        }
    }
    if (!o0 || !o1 || !o2 || !lab) {
        o0 = (const float*)d_in[0];
        o1 = (const float*)d_in[1];
        o2 = (const float*)d_in[2];
        lab = (const float*)d_in[3];
    }

    int totBN = BB * NPRI;
    k_setup<<<(totBN + 255) / 256, 256>>>();
    k_targets<<<BB * LL, 256>>>(lab);
    k_loss<<<(totBN + 255) / 256, 256>>>(o0, o1, o2);
    k_final<<<1, 1>>>((float*)d_out);
}